// round 13
// baseline (speedup 1.0000x reference)
#include <cuda_runtime.h>
#include <math.h>

#define BATCH 16
#define C_IN 103
#define C_CONV 256
#define N_OUT 103
#define D_OUT 16
#define REC 8343
#define H1_DIM 5562
#define H2_DIM 12514
#define K1 1648
#define CONV_G 8

typedef unsigned long long u64;

// ---------------- static device workspace ----------------
__device__ float g_p[BATCH * C_CONV];
__device__ float g_WsumJ[N_OUT * C_CONV * D_OUT];    // [j][c][o]
__device__ float g_s[N_OUT * BATCH * D_OUT];         // [j][b*16+o]
__device__ float g_f0T[K1 * BATCH];                  // [k][b]
__device__ float g_h1T[H1_DIM * BATCH];
__device__ float g_h2T[H2_DIM * BATCH];
__device__ float g_part[4500000];                    // split-K partials
__device__ unsigned g_barcnt = 0;                    // monotonic ticket barrier

// ---------------- helpers ----------------
__device__ __forceinline__ float block_reduce_sum(float v, float* sc) {
    int t = threadIdx.x;
#pragma unroll
    for (int o = 16; o > 0; o >>= 1) v += __shfl_xor_sync(0xffffffffu, v, o);
    if ((t & 31) == 0) sc[t >> 5] = v;
    __syncthreads();
    if (t < 32) {
        float w = (t < 8) ? sc[t] : 0.f;
#pragma unroll
        for (int o = 4; o > 0; o >>= 1) w += __shfl_xor_sync(0xffffffffu, w, o);
        if (t == 0) sc[0] = w;
    }
    __syncthreads();
    float r = sc[0];
    __syncthreads();
    return r;
}

__device__ __forceinline__ float block_reduce_max(float v, float* sc) {
    int t = threadIdx.x;
#pragma unroll
    for (int o = 16; o > 0; o >>= 1) v = fmaxf(v, __shfl_xor_sync(0xffffffffu, v, o));
    if ((t & 31) == 0) sc[t >> 5] = v;
    __syncthreads();
    if (t < 32) {
        float w = (t < 8) ? sc[t] : -1e30f;
#pragma unroll
        for (int o = 4; o > 0; o >>= 1) w = fmaxf(w, __shfl_xor_sync(0xffffffffu, w, o));
        if (t == 0) sc[0] = w;
    }
    __syncthreads();
    float r = sc[0];
    __syncthreads();
    return r;
}

// monotonic-ticket global barrier: no reset, survives graph replays
__device__ __forceinline__ void gbar(unsigned nb) {
    __syncthreads();
    if (threadIdx.x == 0) {
        __threadfence();
        unsigned ticket = atomicAdd(&g_barcnt, 1u);
        unsigned target = (ticket / nb + 1u) * nb;
        while (*(volatile unsigned*)&g_barcnt < target) { __nanosleep(64); }
        __threadfence();
    }
    __syncthreads();
}

// ---------------- conv 3x3 VALID + relu + spatial mean -> p[b][oc] ----------------
__global__ void k_conv_mean(const float* __restrict__ x, const float* __restrict__ w,
                            const float* __restrict__ bias) {
    extern __shared__ float smem[];
    float* sx = smem;
    float* sw = sx + C_IN * 81;
    float* sacc = sw + CONV_G * C_IN * 9;
    int b = blockIdx.y;
    int oc0 = blockIdx.x * CONV_G;
    int t = threadIdx.x;
    for (int i = t; i < C_IN * 81; i += blockDim.x) sx[i] = x[b * C_IN * 81 + i];
    for (int i = t; i < CONV_G * C_IN * 9; i += blockDim.x) sw[i] = w[oc0 * C_IN * 9 + i];
    __syncthreads();
    if (t < CONV_G * 49) {
        int ocl = t / 49, pos = t % 49, oy = pos / 7, ox = pos % 7;
        float acc = bias[oc0 + ocl];
        const float* wp = &sw[ocl * C_IN * 9];
        for (int ic = 0; ic < C_IN; ic++) {
            const float* xp = &sx[ic * 81 + oy * 9 + ox];
            const float* wq = &wp[ic * 9];
#pragma unroll
            for (int ky = 0; ky < 3; ky++)
#pragma unroll
                for (int kx = 0; kx < 3; kx++)
                    acc = fmaf(xp[ky * 9 + kx], wq[ky * 3 + kx], acc);
        }
        sacc[t] = fmaxf(acc, 0.f);
    }
    __syncthreads();
    if (t < CONV_G) {
        float s = 0.f;
#pragma unroll
        for (int i = 0; i < 49; i++) s += sacc[t * 49 + i];
        g_p[b * C_CONV + oc0 + t] = s * (1.f / 49.f);
    }
}

// ---------------- WsumJ[j][c][o] = sum_i W_caps[c][j][o][i] ----------------
__global__ void k_wsum(const float* __restrict__ Wc) {
    int e = blockIdx.x * 256 + threadIdx.x;   // 421888 = C_CONV*N_OUT*16
    const float4* p = (const float4*)(Wc + (size_t)e * 32);
    float s = 0.f;
#pragma unroll
    for (int i = 0; i < 8; i++) {
        float4 v = __ldg(p + i);
        s += (v.x + v.y) + (v.z + v.w);
    }
    int c = e / 1648;
    int r = e - c * 1648;
    int j = r >> 4, o = r & 15;
    g_WsumJ[((j << 8) + c) * 16 + o] = s;
}

// ---------------- single persistent routing kernel (3 iters) + epilogue ----------------
__global__ void k_route(float* __restrict__ dout) {
    __shared__ float shw[C_CONV * 17];
    __shared__ float shq[C_CONV * 17];
    __shared__ float shcq[C_CONV * 17];
    __shared__ float shc[C_CONV];
    __shared__ float shv[256];
    __shared__ float shba[16];
    __shared__ float sc[8];
    int j = blockIdx.x, t = threadIdx.x;

    for (int b = 0; b < BATCH; b++) {
        float v = g_p[b * 256 + t];
        float msq = block_reduce_sum(v * v, sc);
        shq[t * 17 + b] = v * sqrtf(msq) / (1.f + msq);
    }
    const float4* wj = (const float4*)(g_WsumJ + (size_t)j * 4096);
#pragma unroll
    for (int r = 0; r < 4; r++) {
        int i4 = r * 256 + t;
        float4 v = wj[i4];
        int c = i4 >> 2, o = (i4 & 3) * 4;
        shw[c * 17 + o] = v.x; shw[c * 17 + o + 1] = v.y;
        shw[c * 17 + o + 2] = v.z; shw[c * 17 + o + 3] = v.w;
    }
    float bv = 1.f;
    __syncthreads();

    int bb = t >> 4, oo = t & 15;
    for (int it = 0; it < 3; it++) {
        float m = block_reduce_max(bv, sc);
        float e = expf(bv - m);
        float ssum = block_reduce_sum(e, sc);
        shc[t] = e / ssum;
        __syncthreads();
        for (int i = t; i < 4096; i += 256) {
            int c = i >> 4, b = i & 15;
            shcq[c * 17 + b] = shc[c] * shq[c * 17 + b];
        }
        __syncthreads();
        float acc = 0.f;
#pragma unroll 8
        for (int c = 0; c < 256; c++) acc = fmaf(shcq[c * 17 + bb], shw[c * 17 + oo], acc);
        __stcg(&g_s[j * 256 + t], acc);
        gbar(N_OUT);
        float msq = 0.f;
#pragma unroll 4
        for (int jj = 0; jj < N_OUT; jj++) {
            float sv = __ldcg(&g_s[jj * 256 + t]);
            msq = fmaf(sv, sv, msq);
        }
        float vv = acc * sqrtf(msq) / (1.f + msq);
        shv[t] = vv;
        __syncthreads();
        if (it < 2) {
            float g = 0.f;
#pragma unroll
            for (int b2 = 0; b2 < BATCH; b2++) {
                float d = 0.f;
#pragma unroll
                for (int o2 = 0; o2 < 16; o2++) d = fmaf(shw[t * 17 + o2], shv[b2 * 16 + o2], d);
                g = fmaf(shq[t * 17 + b2], d, g);
            }
            bv += g * (1.f / 16.f);
            gbar(N_OUT);
        }
    }
    if (t < 16) {
        float r = 0.f;
#pragma unroll
        for (int o2 = 0; o2 < 16; o2++) { float q = shv[t * 16 + o2]; r = fmaf(q, q, r); }
        float ba = sqrtf(r);
        shba[t] = ba;
        dout[t * N_OUT + j] = ba;
    }
    __syncthreads();
    g_f0T[(j * 16 + oo) * 16 + bb] = shv[t] * shba[bb];
}

// ---------------- skinny GEMM (M=16): forced-MLP volatile LDG, split-K ----------------
#define FMA8(ACC, A0, A1, A2, A3, WP)                                               \
    asm("fma.rn.f32x2 %0,%1,%2,%0;" : "+l"(ACC[0]) : "l"(A0.x), "l"(WP));           \
    asm("fma.rn.f32x2 %0,%1,%2,%0;" : "+l"(ACC[1]) : "l"(A0.y), "l"(WP));           \
    asm("fma.rn.f32x2 %0,%1,%2,%0;" : "+l"(ACC[2]) : "l"(A1.x), "l"(WP));           \
    asm("fma.rn.f32x2 %0,%1,%2,%0;" : "+l"(ACC[3]) : "l"(A1.y), "l"(WP));           \
    asm("fma.rn.f32x2 %0,%1,%2,%0;" : "+l"(ACC[4]) : "l"(A2.x), "l"(WP));           \
    asm("fma.rn.f32x2 %0,%1,%2,%0;" : "+l"(ACC[5]) : "l"(A2.y), "l"(WP));           \
    asm("fma.rn.f32x2 %0,%1,%2,%0;" : "+l"(ACC[6]) : "l"(A3.x), "l"(WP));           \
    asm("fma.rn.f32x2 %0,%1,%2,%0;" : "+l"(ACC[7]) : "l"(A3.y), "l"(WP));

#define LDGV(dst, ptr) \
    asm volatile("ld.global.nc.f32 %0,[%1];" : "=f"(dst) : "l"(ptr))

#define CBLK 512
#define UB 8

__global__ __launch_bounds__(256, 3) void k_fc_part(int insel, const float* __restrict__ W,
                                                    int K, int N, int kchunk) {
    extern __shared__ float sa[];          // (kchunk padded to UB) * 16, zero-filled tail
    const float* inT = (insel == 0) ? g_f0T : (insel == 1) ? g_h1T : g_h2T;
    int t = threadIdx.x;
    int k0 = blockIdx.y * kchunk;
    int kn = min(K - k0, kchunk);
    int knp = (kn + UB - 1) & ~(UB - 1);
    int nblk = blockIdx.x * CBLK;
    // stage A chunk (zero-pad beyond kn so tail k contribute 0)
    for (int i = t; i < knp * 16; i += 256) {
        sa[i] = (i < kn * 16) ? inT[(size_t)k0 * 16 + i] : 0.f;
    }
    __syncthreads();

    int n0 = nblk + t;
    int n1 = n0 + 256;
    int n0c = (n0 < N) ? n0 : 0;           // clamped (garbage acc discarded at store)
    int n1c = (n1 < N) ? n1 : 0;

    u64 acc[2][8];
#pragma unroll
    for (int i = 0; i < 2; i++)
#pragma unroll
        for (int b = 0; b < 8; b++) acc[i][b] = 0ull;

    const float* Wr = W + (size_t)k0 * N;
    long long strideN = (long long)N;
    int kfull = kn & ~(UB - 1);            // full batches, no k-clamp needed

    int kb = 0;
#pragma unroll 1
    for (; kb < kfull; kb += UB) {
        float w0[UB], w1[UB];
        const float* p = Wr + (size_t)kb * N;
        // phase 1: 16 independent loads, order forced by volatile
#pragma unroll
        for (int r = 0; r < UB; r++) {
            LDGV(w0[r], p + n0c);
            LDGV(w1[r], p + n1c);
            p += strideN;
        }
        // phase 2: consume
        const float* sar = sa + kb * 16;
#pragma unroll
        for (int r = 0; r < UB; r++) {
            const ulonglong2* ap = (const ulonglong2*)(sar + r * 16);
            ulonglong2 A0 = ap[0], A1 = ap[1], A2 = ap[2], A3 = ap[3];
            u64 wp_;
            asm("mov.b64 %0,{%1,%1};" : "=l"(wp_) : "f"(w0[r]));
            FMA8(acc[0], A0, A1, A2, A3, wp_)
            asm("mov.b64 %0,{%1,%1};" : "=l"(wp_) : "f"(w1[r]));
            FMA8(acc[1], A0, A1, A2, A3, wp_)
        }
    }
    if (kb < kn) {
        // tail batch: clamp k (A is zero beyond kn, so clamped rows contribute 0)
        float w0[UB], w1[UB];
#pragma unroll
        for (int r = 0; r < UB; r++) {
            int kk = kb + r; if (kk >= kn) kk = kn - 1;
            const float* p = Wr + (size_t)kk * N;
            LDGV(w0[r], p + n0c);
            LDGV(w1[r], p + n1c);
        }
        const float* sar = sa + kb * 16;
#pragma unroll
        for (int r = 0; r < UB; r++) {
            const ulonglong2* ap = (const ulonglong2*)(sar + r * 16);
            ulonglong2 A0 = ap[0], A1 = ap[1], A2 = ap[2], A3 = ap[3];
            u64 wp_;
            asm("mov.b64 %0,{%1,%1};" : "=l"(wp_) : "f"(w0[r]));
            FMA8(acc[0], A0, A1, A2, A3, wp_)
            asm("mov.b64 %0,{%1,%1};" : "=l"(wp_) : "f"(w1[r]));
            FMA8(acc[1], A0, A1, A2, A3, wp_)
        }
    }

#pragma unroll
    for (int i = 0; i < 2; i++) {
        int n = nblk + t + 256 * i;
        if (n < N) {
            ulonglong2* dst = (ulonglong2*)&g_part[((size_t)blockIdx.y * N + n) * 16];
            dst[0] = make_ulonglong2(acc[i][0], acc[i][1]);
            dst[1] = make_ulonglong2(acc[i][2], acc[i][3]);
            dst[2] = make_ulonglong2(acc[i][4], acc[i][5]);
            dst[3] = make_ulonglong2(acc[i][6], acc[i][7]);
        }
    }
}

// ---------------- split-K reduce + bias ----------------
__global__ void k_fc_reduce(const float* __restrict__ bias, int outsel, int N, int ks,
                            float* __restrict__ dout) {
    int gid = blockIdx.x * 256 + threadIdx.x;
    if (gid >= N * 16) return;
    int n = gid >> 4, b = gid & 15;
    float s = __ldg(bias + n);
#pragma unroll 4
    for (int j = 0; j < ks; j++) s += g_part[((size_t)j * N + n) * 16 + b];
    if (outsel == 3) dout[1648 + b * REC + n] = s;
    else if (outsel == 1) g_h1T[gid] = s;
    else g_h2T[gid] = s;
}

// ---------------- launch ----------------
extern "C" void kernel_launch(void* const* d_in, const int* in_sizes, int n_in,
                              void* d_out, int out_size) {
    const float* x   = (const float*)d_in[0];
    const float* cw  = (const float*)d_in[1];
    const float* cb  = (const float*)d_in[2];
    const float* Wc  = (const float*)d_in[3];
    const float* f1w = (const float*)d_in[4];
    const float* f1b = (const float*)d_in[5];
    const float* f2w = (const float*)d_in[6];
    const float* f2b = (const float*)d_in[7];
    const float* f3w = (const float*)d_in[8];
    const float* f3b = (const float*)d_in[9];
    float* out = (float*)d_out;

    int conv_smem = (C_IN * 81 + CONV_G * C_IN * 9 + CONV_G * 49) * 4;
    static int attr_set = 0;
    if (!attr_set) {
        cudaFuncSetAttribute(k_conv_mean, cudaFuncAttributeMaxDynamicSharedMemorySize, conv_smem);
        attr_set = 1;
    }
    auto asmem = [](int kchunk) { return ((kchunk + UB - 1) & ~(UB - 1)) * 16 * 4; };

    k_conv_mean<<<dim3(C_CONV / CONV_G, BATCH), 512, conv_smem>>>(x, cw, cb);
    k_wsum<<<1648, 256>>>(Wc);
    k_route<<<N_OUT, 256>>>(out);
    // fc1: K=1648 N=5562: 11 n-blocks × ks=40 = 440 blocks, chunk 42
    k_fc_part<<<dim3(11, 40), 256, asmem(42)>>>(0, f1w, K1, H1_DIM, 42);
    k_fc_reduce<<<348, 256>>>(f1b, 1, H1_DIM, 40, out);
    // fc2: K=5562 N=12514: 25 n-blocks × ks=17 = 425 blocks, chunk 328
    k_fc_part<<<dim3(25, 17), 256, asmem(328)>>>(1, f2w, H1_DIM, H2_DIM, 328);
    k_fc_reduce<<<783, 256>>>(f2b, 2, H2_DIM, 17, out);
    // fc3: K=12514 N=8343: 17 n-blocks × ks=26 = 442 blocks, chunk 482
    k_fc_part<<<dim3(17, 26), 256, asmem(482)>>>(2, f3w, H2_DIM, REC, 482);
    k_fc_reduce<<<522, 256>>>(f3b, 3, REC, 26, out);
}